// round 2
// baseline (speedup 1.0000x reference)
#include <cuda_runtime.h>
#include <cstdint>

#define N_ROWS   16384
#define DMODEL   768
#define DLATENT  12288
#define TOPK     20
#define KCAND    32

// ---- scratch (no allocation allowed -> __device__ globals) ----
__device__ float g_lat[(size_t)N_ROWS * DLATENT];    // 805 MB latents
__device__ int   g_cidx[N_ROWS * KCAND];             // top-32 candidate indices
__device__ float g_vals[N_ROWS * TOPK];
__device__ int   g_idx [N_ROWS * TOPK];
__device__ float g_WdecT[(size_t)DLATENT * DMODEL];  // 37.7 MB

__device__ __forceinline__ float f2tf32(float x) {
    uint32_t u;
    asm("cvt.rna.tf32.f32 %0, %1;" : "=r"(u) : "f"(x));
    return __uint_as_float(u);
}

// ============================================================
// Kernel 0: transpose W_dec [768,12288] -> W_decT [12288,768]
// ============================================================
__global__ void transpose_wdec(const float* __restrict__ Wdec) {
    __shared__ float tile[32][33];
    int l0 = blockIdx.x * 32;
    int d0 = blockIdx.y * 32;
    int tx = threadIdx.x, ty = threadIdx.y;   // (32,8)
    #pragma unroll
    for (int r = 0; r < 32; r += 8)
        tile[ty + r][tx] = Wdec[(size_t)(d0 + ty + r) * DLATENT + l0 + tx];
    __syncthreads();
    #pragma unroll
    for (int r = 0; r < 32; r += 8)
        g_WdecT[(size_t)(l0 + ty + r) * DMODEL + d0 + tx] = tile[tx][ty + r];
}

// ============================================================
// Kernel 1: encode GEMM  latents = X * W_enc^T + b_enc (tf32, approximate)
// ============================================================
#define BM 128
#define BN 128
#define BK 32
#define BKP 36

__global__ __launch_bounds__(256, 2)
void encode_gemm(const float* __restrict__ X,
                 const float* __restrict__ W,
                 const float* __restrict__ benc) {
    __shared__ float As[BM * BKP];
    __shared__ float Bs[BN * BKP];

    const int t    = threadIdx.x;
    const int bm   = blockIdx.y;
    const int bn   = blockIdx.x;
    const int w    = t >> 5;
    const int lane = t & 31;
    const int wm   = (w >> 2) * 64;
    const int wn   = (w & 3) * 32;
    const int grp  = lane >> 2;
    const int qid  = lane & 3;

    float c[4][4][4];
    #pragma unroll
    for (int i = 0; i < 4; ++i)
        #pragma unroll
        for (int j = 0; j < 4; ++j)
            #pragma unroll
            for (int q = 0; q < 4; ++q) c[i][j][q] = 0.f;

    const int lrow = t >> 3;
    const int lk   = (t & 7) * 4;
    const float* Ag = X + (size_t)(bm * BM + lrow) * DMODEL + lk;
    const float* Bg = W + (size_t)(bn * BN + lrow) * DMODEL + lk;

    for (int kt = 0; kt < DMODEL; kt += BK) {
        #pragma unroll
        for (int r = 0; r < 4; ++r) {
            float4 va = *(const float4*)(Ag + (size_t)(r * 32) * DMODEL + kt);
            float4 vb = *(const float4*)(Bg + (size_t)(r * 32) * DMODEL + kt);
            int row = lrow + r * 32;
            float* pa = &As[row * BKP + lk];
            pa[0] = f2tf32(va.x); pa[1] = f2tf32(va.y);
            pa[2] = f2tf32(va.z); pa[3] = f2tf32(va.w);
            float* pb = &Bs[row * BKP + lk];
            pb[0] = f2tf32(vb.x); pb[1] = f2tf32(vb.y);
            pb[2] = f2tf32(vb.z); pb[3] = f2tf32(vb.w);
        }
        __syncthreads();

        #pragma unroll
        for (int ks = 0; ks < 4; ++ks) {
            const int k8 = ks * 8;
            uint32_t a[4][4], bf[4][2];
            #pragma unroll
            for (int i = 0; i < 4; ++i) {
                int rb = wm + i * 16;
                a[i][0] = __float_as_uint(As[(rb + grp    ) * BKP + k8 + qid    ]);
                a[i][1] = __float_as_uint(As[(rb + grp + 8) * BKP + k8 + qid    ]);
                a[i][2] = __float_as_uint(As[(rb + grp    ) * BKP + k8 + qid + 4]);
                a[i][3] = __float_as_uint(As[(rb + grp + 8) * BKP + k8 + qid + 4]);
            }
            #pragma unroll
            for (int j = 0; j < 4; ++j) {
                int cb = wn + j * 8;
                bf[j][0] = __float_as_uint(Bs[(cb + grp) * BKP + k8 + qid    ]);
                bf[j][1] = __float_as_uint(Bs[(cb + grp) * BKP + k8 + qid + 4]);
            }
            #pragma unroll
            for (int i = 0; i < 4; ++i)
                #pragma unroll
                for (int j = 0; j < 4; ++j) {
                    asm volatile(
                        "mma.sync.aligned.m16n8k8.row.col.f32.tf32.tf32.f32 "
                        "{%0,%1,%2,%3}, {%4,%5,%6,%7}, {%8,%9}, {%0,%1,%2,%3};"
                        : "+f"(c[i][j][0]), "+f"(c[i][j][1]),
                          "+f"(c[i][j][2]), "+f"(c[i][j][3])
                        : "r"(a[i][0]), "r"(a[i][1]), "r"(a[i][2]), "r"(a[i][3]),
                          "r"(bf[j][0]), "r"(bf[j][1]));
                }
        }
        __syncthreads();
    }

    #pragma unroll
    for (int j = 0; j < 4; ++j) {
        int cg = bn * BN + wn + j * 8 + 2 * qid;
        float b0 = benc[cg], b1 = benc[cg + 1];
        #pragma unroll
        for (int i = 0; i < 4; ++i) {
            int rg = bm * BM + wm + i * 16 + grp;
            float2 v0 = make_float2(c[i][j][0] + b0, c[i][j][1] + b1);
            float2 v1 = make_float2(c[i][j][2] + b0, c[i][j][3] + b1);
            *(float2*)&g_lat[(size_t)rg * DLATENT + cg]       = v0;
            *(float2*)&g_lat[(size_t)(rg + 8) * DLATENT + cg] = v1;
        }
    }
}

// ============================================================
// Kernel 2: per-row top-32 CANDIDATE indices from tf32 latents.
// tf32 error (~4e-4) << rank20->rank32 value span (~0.18), so the
// exact top-20 is always contained in the tf32 top-32.
// ============================================================
__global__ __launch_bounds__(128)
void topk_cand_kernel() {
    const int row = blockIdx.x;
    const int t   = threadIdx.x;   // 128
    const float* lat = g_lat + (size_t)row * DLATENT;

    float lv[KCAND];
    int   li[KCAND];
    #pragma unroll
    for (int k = 0; k < KCAND; ++k) { lv[k] = -3.4e38f; li[k] = 0; }

    for (int col = t; col < DLATENT; col += 128) {
        float v = lat[col];
        if (v > lv[KCAND - 1]) {
            int p = KCAND - 1;
            while (p > 0 && lv[p - 1] < v) {
                lv[p] = lv[p - 1]; li[p] = li[p - 1]; --p;
            }
            lv[p] = v; li[p] = col;
        }
    }

    __shared__ float sv[128 * KCAND];
    __shared__ int   si[128 * KCAND];
    __shared__ float rv[128];
    __shared__ int   rs[128];
    #pragma unroll
    for (int k = 0; k < KCAND; ++k) { sv[t * KCAND + k] = lv[k]; si[t * KCAND + k] = li[k]; }
    __syncthreads();

    for (int kk = 0; kk < KCAND; ++kk) {
        float m = -3.4e38f; int ms = 0;
        #pragma unroll
        for (int k = 0; k < KCAND; ++k) {
            int s = t * KCAND + k;
            if (sv[s] > m) { m = sv[s]; ms = s; }
        }
        rv[t] = m; rs[t] = ms;
        __syncthreads();
        for (int off = 64; off > 0; off >>= 1) {
            if (t < off && rv[t + off] > rv[t]) { rv[t] = rv[t + off]; rs[t] = rs[t + off]; }
            __syncthreads();
        }
        if (t == 0) {
            int s = rs[0];
            g_cidx[row * KCAND + kk] = si[s];
            sv[s] = -3.4e38f;
        }
        __syncthreads();
    }
}

// ============================================================
// Kernel 3: fp64 refinement — recompute the 32 candidate latents
// exactly, select the true top-20.
// ============================================================
__global__ __launch_bounds__(256)
void refine_kernel(const float* __restrict__ X,
                   const float* __restrict__ W,
                   const float* __restrict__ benc) {
    const int row  = blockIdx.x;
    const int t    = threadIdx.x;    // 256 = 8 warps
    const int w    = t >> 5;
    const int lane = t & 31;

    __shared__ float  xs[DMODEL];
    __shared__ double cv[KCAND];
    __shared__ int    ci[KCAND];

    for (int j = t; j < DMODEL; j += 256)
        xs[j] = X[(size_t)row * DMODEL + j];
    __syncthreads();

    #pragma unroll
    for (int cb = 0; cb < KCAND; cb += 8) {
        int c   = cb + w;
        int idx = g_cidx[row * KCAND + c];
        const float* wr = W + (size_t)idx * DMODEL;
        double acc = 0.0;
        #pragma unroll
        for (int j = 0; j < DMODEL / 32; ++j)
            acc += (double)xs[lane + j * 32] * (double)wr[lane + j * 32];
        #pragma unroll
        for (int off = 16; off > 0; off >>= 1)
            acc += __shfl_down_sync(0xffffffffu, acc, off);
        if (lane == 0) { cv[c] = acc + (double)benc[idx]; ci[c] = idx; }
    }
    __syncthreads();

    if (t == 0) {
        #pragma unroll
        for (int kk = 0; kk < TOPK; ++kk) {
            double m = -1e300; int ms = 0;
            #pragma unroll
            for (int k = 0; k < KCAND; ++k)
                if (cv[k] > m) { m = cv[k]; ms = k; }
            g_vals[row * TOPK + kk] = (float)m;
            g_idx [row * TOPK + kk] = ci[ms];
            cv[ms] = -1e300;
        }
    }
}

// ============================================================
// Kernel 4: decode  out[n,d] = b_dec[d] + sum_k vals[n,k]*W_decT[idx[n,k], d]
// ============================================================
__global__ __launch_bounds__(256)
void decode_kernel(const float* __restrict__ bdec,
                   float* __restrict__ out) {
    const int row = blockIdx.x;
    const int t   = threadIdx.x;   // 256
    __shared__ float v[TOPK];
    __shared__ int   id[TOPK];
    if (t < TOPK) { v[t] = g_vals[row * TOPK + t]; id[t] = g_idx[row * TOPK + t]; }
    __syncthreads();

    #pragma unroll
    for (int r = 0; r < 3; ++r) {
        int d = t + r * 256;
        float acc = bdec[d];
        #pragma unroll
        for (int k = 0; k < TOPK; ++k)
            acc += v[k] * g_WdecT[(size_t)id[k] * DMODEL + d];
        out[(size_t)row * DMODEL + d] = acc;
    }
}

// ============================================================
extern "C" void kernel_launch(void* const* d_in, const int* in_sizes, int n_in,
                              void* d_out, int out_size) {
    const float* x     = (const float*)d_in[0];
    const float* W_enc = (const float*)d_in[1];
    const float* b_enc = (const float*)d_in[2];
    const float* W_dec = (const float*)d_in[3];
    const float* b_dec = (const float*)d_in[4];
    float* out = (float*)d_out;

    transpose_wdec<<<dim3(DLATENT / 32, DMODEL / 32), dim3(32, 8)>>>(W_dec);
    encode_gemm<<<dim3(DLATENT / BN, N_ROWS / BM), 256>>>(x, W_enc, b_enc);
    topk_cand_kernel<<<N_ROWS, 128>>>();
    refine_kernel<<<N_ROWS, 256>>>(x, W_enc, b_enc);
    decode_kernel<<<N_ROWS, 256>>>(b_dec, out);
}

// round 3
// speedup vs baseline: 1.0096x; 1.0096x over previous
#include <cuda_runtime.h>
#include <cstdint>

#define N_ROWS   16384
#define DMODEL   768
#define DLATENT  12288
#define TOPK     20
#define KCAND    32

// ---- scratch (no allocation allowed -> __device__ globals) ----
__device__ float g_lat[(size_t)N_ROWS * DLATENT];    // 805 MB latents
__device__ int   g_cidx[N_ROWS * KCAND];             // top-32 candidate indices
__device__ float g_vals[N_ROWS * TOPK];
__device__ int   g_idx [N_ROWS * TOPK];
__device__ float g_WdecT[(size_t)DLATENT * DMODEL];  // 37.7 MB

// ============================================================
// Kernel 0: transpose W_dec [768,12288] -> W_decT [12288,768]
// ============================================================
__global__ void transpose_wdec(const float* __restrict__ Wdec) {
    __shared__ float tile[32][33];
    int l0 = blockIdx.x * 32;
    int d0 = blockIdx.y * 32;
    int tx = threadIdx.x, ty = threadIdx.y;   // (32,8)
    #pragma unroll
    for (int r = 0; r < 32; r += 8)
        tile[ty + r][tx] = Wdec[(size_t)(d0 + ty + r) * DLATENT + l0 + tx];
    __syncthreads();
    #pragma unroll
    for (int r = 0; r < 32; r += 8)
        g_WdecT[(size_t)(l0 + ty + r) * DMODEL + d0 + tx] = tile[tx][ty + r];
}

// ============================================================
// Kernel 1: encode GEMM  latents = X * W_enc^T + b_enc (tf32)
//   CTA 128x128x32, 3-stage cp.async pipeline, ldmatrix fragments.
// ============================================================
#define BM 128
#define BN 128
#define BK 32
#define BKP 36                      // padded row stride (floats)
#define STAGE_FLOATS (2 * BM * BKP) // A + B per stage = 9216 floats
#define STAGE_BYTES  (STAGE_FLOATS * 4)
#define NSTAGE 3
#define GEMM_SMEM (NSTAGE * STAGE_BYTES)   // 110592 bytes

__device__ __forceinline__ void cp16(uint32_t dst, const float* src) {
    asm volatile("cp.async.cg.shared.global [%0], [%1], 16;" :: "r"(dst), "l"(src));
}
__device__ __forceinline__ void ldsm4(uint32_t& r0, uint32_t& r1,
                                      uint32_t& r2, uint32_t& r3, uint32_t addr) {
    asm volatile("ldmatrix.sync.aligned.m8n8.x4.shared.b16 {%0,%1,%2,%3}, [%4];"
                 : "=r"(r0), "=r"(r1), "=r"(r2), "=r"(r3) : "r"(addr));
}

extern __shared__ float dynsmem[];

__global__ __launch_bounds__(256)
void encode_gemm(const float* __restrict__ X,
                 const float* __restrict__ W,
                 const float* __restrict__ benc) {
    const int t    = threadIdx.x;
    const int bm   = blockIdx.y;
    const int bn   = blockIdx.x;
    const int w    = t >> 5;
    const int lane = t & 31;
    const int wm   = (w >> 2) * 64;
    const int wn   = (w & 3) * 32;
    const int grp  = lane >> 2;
    const int qid  = lane & 3;

    const uint32_t smem_base = (uint32_t)__cvta_generic_to_shared(dynsmem);

    // ---- loader addressing: thread t loads 4 A-rows + 4 B-rows, 16B each
    const int lrow = t >> 3;          // 0..31
    const int lk   = (t & 7) * 4;     // 0,4,...,28
    const float* Ag = X + (size_t)(bm * BM + lrow) * DMODEL + lk;
    const float* Bg = W + (size_t)(bn * BN + lrow) * DMODEL + lk;
    const uint32_t sA = smem_base + (lrow * BKP + lk) * 4;
    const uint32_t sB = sA + BM * BKP * 4;

    // ---- ldmatrix per-lane addresses
    const int arow = lane & 15;
    const int acol = (lane & 16) ? 4 : 0;
    const int brow = (lane & 7) + ((lane & 16) >> 1);
    const int bcol = (lane & 8) ? 4 : 0;
    const uint32_t aBase = smem_base + ((wm + arow) * BKP + acol) * 4;
    const uint32_t bBase = smem_base + BM * BKP * 4 + ((wn + brow) * BKP + bcol) * 4;

    float c[4][4][4];
    #pragma unroll
    for (int i = 0; i < 4; ++i)
        #pragma unroll
        for (int j = 0; j < 4; ++j)
            #pragma unroll
            for (int q = 0; q < 4; ++q) c[i][j][q] = 0.f;

    const int KT = DMODEL / BK;       // 24

    // prefetch stages 0..NSTAGE-2
    #pragma unroll
    for (int s = 0; s < NSTAGE - 1; ++s) {
        #pragma unroll
        for (int r = 0; r < 4; ++r) {
            cp16(sA + s * STAGE_BYTES + r * 32 * BKP * 4, Ag + s * BK + (size_t)r * 32 * DMODEL);
            cp16(sB + s * STAGE_BYTES + r * 32 * BKP * 4, Bg + s * BK + (size_t)r * 32 * DMODEL);
        }
        asm volatile("cp.async.commit_group;");
    }

    for (int kt = 0; kt < KT; ++kt) {
        asm volatile("cp.async.wait_group %0;" :: "n"(NSTAGE - 2));
        __syncthreads();

        // issue prefetch for kt + NSTAGE-1
        {
            int nxt = kt + NSTAGE - 1;
            if (nxt < KT) {
                int s = nxt % NSTAGE;
                #pragma unroll
                for (int r = 0; r < 4; ++r) {
                    cp16(sA + s * STAGE_BYTES + r * 32 * BKP * 4, Ag + nxt * BK + (size_t)r * 32 * DMODEL);
                    cp16(sB + s * STAGE_BYTES + r * 32 * BKP * 4, Bg + nxt * BK + (size_t)r * 32 * DMODEL);
                }
            }
            asm volatile("cp.async.commit_group;");
        }

        const uint32_t stoff = (uint32_t)(kt % NSTAGE) * STAGE_BYTES;

        #pragma unroll
        for (int ks = 0; ks < 4; ++ks) {
            const int k8 = ks * 8;
            uint32_t a[4][4], bf[4][2];
            #pragma unroll
            for (int i = 0; i < 4; ++i)
                ldsm4(a[i][0], a[i][1], a[i][2], a[i][3],
                      aBase + stoff + (i * 16 * BKP + k8) * 4);
            #pragma unroll
            for (int jp = 0; jp < 2; ++jp)
                ldsm4(bf[2 * jp][0], bf[2 * jp][1], bf[2 * jp + 1][0], bf[2 * jp + 1][1],
                      bBase + stoff + (jp * 16 * BKP + k8) * 4);
            #pragma unroll
            for (int i = 0; i < 4; ++i)
                #pragma unroll
                for (int j = 0; j < 4; ++j) {
                    asm volatile(
                        "mma.sync.aligned.m16n8k8.row.col.f32.tf32.tf32.f32 "
                        "{%0,%1,%2,%3}, {%4,%5,%6,%7}, {%8,%9}, {%0,%1,%2,%3};"
                        : "+f"(c[i][j][0]), "+f"(c[i][j][1]),
                          "+f"(c[i][j][2]), "+f"(c[i][j][3])
                        : "r"(a[i][0]), "r"(a[i][1]), "r"(a[i][2]), "r"(a[i][3]),
                          "r"(bf[j][0]), "r"(bf[j][1]));
                }
        }
    }

    // epilogue: + b_enc, store latents
    #pragma unroll
    for (int j = 0; j < 4; ++j) {
        int cg = bn * BN + wn + j * 8 + 2 * qid;
        float b0 = benc[cg], b1 = benc[cg + 1];
        #pragma unroll
        for (int i = 0; i < 4; ++i) {
            int rg = bm * BM + wm + i * 16 + grp;
            float2 v0 = make_float2(c[i][j][0] + b0, c[i][j][1] + b1);
            float2 v1 = make_float2(c[i][j][2] + b0, c[i][j][3] + b1);
            *(float2*)&g_lat[(size_t)rg * DLATENT + cg]       = v0;
            *(float2*)&g_lat[(size_t)(rg + 8) * DLATENT + cg] = v1;
        }
    }
}

// ============================================================
// Kernel 2: per-row top-32 CANDIDATE indices from tf32 latents.
// tf32 error (<~1e-3) << rank20->rank32 value span (~0.18), so the
// exact top-20 is always contained in the tf32 top-32.
// ============================================================
__global__ __launch_bounds__(128)
void topk_cand_kernel() {
    const int row = blockIdx.x;
    const int t   = threadIdx.x;   // 128
    const float* lat = g_lat + (size_t)row * DLATENT;

    float lv[KCAND];
    int   li[KCAND];
    #pragma unroll
    for (int k = 0; k < KCAND; ++k) { lv[k] = -3.4e38f; li[k] = 0; }

    for (int col = t; col < DLATENT; col += 128) {
        float v = lat[col];
        if (v > lv[KCAND - 1]) {
            int p = KCAND - 1;
            while (p > 0 && lv[p - 1] < v) {
                lv[p] = lv[p - 1]; li[p] = li[p - 1]; --p;
            }
            lv[p] = v; li[p] = col;
        }
    }

    __shared__ float sv[128 * KCAND];
    __shared__ int   si[128 * KCAND];
    __shared__ float rv[128];
    __shared__ int   rs[128];
    #pragma unroll
    for (int k = 0; k < KCAND; ++k) { sv[t * KCAND + k] = lv[k]; si[t * KCAND + k] = li[k]; }
    __syncthreads();

    for (int kk = 0; kk < KCAND; ++kk) {
        float m = -3.4e38f; int ms = 0;
        #pragma unroll
        for (int k = 0; k < KCAND; ++k) {
            int s = t * KCAND + k;
            if (sv[s] > m) { m = sv[s]; ms = s; }
        }
        rv[t] = m; rs[t] = ms;
        __syncthreads();
        for (int off = 64; off > 0; off >>= 1) {
            if (t < off && rv[t + off] > rv[t]) { rv[t] = rv[t + off]; rs[t] = rs[t + off]; }
            __syncthreads();
        }
        if (t == 0) {
            int s = rs[0];
            g_cidx[row * KCAND + kk] = si[s];
            sv[s] = -3.4e38f;
        }
        __syncthreads();
    }
}

// ============================================================
// Kernel 3: fp64 refinement — recompute the 32 candidate latents
// exactly, select the true top-20.
// ============================================================
__global__ __launch_bounds__(256)
void refine_kernel(const float* __restrict__ X,
                   const float* __restrict__ W,
                   const float* __restrict__ benc) {
    const int row  = blockIdx.x;
    const int t    = threadIdx.x;    // 256 = 8 warps
    const int w    = t >> 5;
    const int lane = t & 31;

    __shared__ float  xs[DMODEL];
    __shared__ double cv[KCAND];
    __shared__ int    ci[KCAND];

    for (int j = t; j < DMODEL; j += 256)
        xs[j] = X[(size_t)row * DMODEL + j];
    __syncthreads();

    #pragma unroll
    for (int cb = 0; cb < KCAND; cb += 8) {
        int c   = cb + w;
        int idx = g_cidx[row * KCAND + c];
        const float* wr = W + (size_t)idx * DMODEL;
        double acc = 0.0;
        #pragma unroll
        for (int j = 0; j < DMODEL / 32; ++j)
            acc += (double)xs[lane + j * 32] * (double)wr[lane + j * 32];
        #pragma unroll
        for (int off = 16; off > 0; off >>= 1)
            acc += __shfl_down_sync(0xffffffffu, acc, off);
        if (lane == 0) { cv[c] = acc + (double)benc[idx]; ci[c] = idx; }
    }
    __syncthreads();

    if (t == 0) {
        #pragma unroll
        for (int kk = 0; kk < TOPK; ++kk) {
            double m = -1e300; int ms = 0;
            #pragma unroll
            for (int k = 0; k < KCAND; ++k)
                if (cv[k] > m) { m = cv[k]; ms = k; }
            g_vals[row * TOPK + kk] = (float)m;
            g_idx [row * TOPK + kk] = ci[ms];
            cv[ms] = -1e300;
        }
    }
}

// ============================================================
// Kernel 4: decode  out[n,d] = b_dec[d] + sum_k vals[n,k]*W_decT[idx[n,k], d]
// ============================================================
__global__ __launch_bounds__(256)
void decode_kernel(const float* __restrict__ bdec,
                   float* __restrict__ out) {
    const int row = blockIdx.x;
    const int t   = threadIdx.x;   // 256
    __shared__ float v[TOPK];
    __shared__ int   id[TOPK];
    if (t < TOPK) { v[t] = g_vals[row * TOPK + t]; id[t] = g_idx[row * TOPK + t]; }
    __syncthreads();

    #pragma unroll
    for (int r = 0; r < 3; ++r) {
        int d = t + r * 256;
        float acc = bdec[d];
        #pragma unroll
        for (int k = 0; k < TOPK; ++k)
            acc += v[k] * g_WdecT[(size_t)id[k] * DMODEL + d];
        out[(size_t)row * DMODEL + d] = acc;
    }
}

// ============================================================
extern "C" void kernel_launch(void* const* d_in, const int* in_sizes, int n_in,
                              void* d_out, int out_size) {
    const float* x     = (const float*)d_in[0];
    const float* W_enc = (const float*)d_in[1];
    const float* b_enc = (const float*)d_in[2];
    const float* W_dec = (const float*)d_in[3];
    const float* b_dec = (const float*)d_in[4];
    float* out = (float*)d_out;

    cudaFuncSetAttribute(encode_gemm, cudaFuncAttributeMaxDynamicSharedMemorySize, GEMM_SMEM);

    transpose_wdec<<<dim3(DLATENT / 32, DMODEL / 32), dim3(32, 8)>>>(W_dec);
    encode_gemm<<<dim3(DLATENT / BN, N_ROWS / BM), 256, GEMM_SMEM>>>(x, W_enc, b_enc);
    topk_cand_kernel<<<N_ROWS, 128>>>();
    refine_kernel<<<N_ROWS, 256>>>(x, W_enc, b_enc);
    decode_kernel<<<N_ROWS, 256>>>(b_dec, out);
}

// round 4
// speedup vs baseline: 1.0974x; 1.0869x over previous
#include <cuda_runtime.h>
#include <cstdint>

#define N_ROWS   16384
#define DMODEL   768
#define DLATENT  12288
#define TOPK     20
#define KCAND    32

// ---- scratch (no allocation allowed -> __device__ globals) ----
__device__ float g_lat[(size_t)N_ROWS * DLATENT];    // 805 MB latents
__device__ int   g_cidx[N_ROWS * KCAND];             // top-32 candidate indices
__device__ float g_vals[N_ROWS * TOPK];
__device__ int   g_idx [N_ROWS * TOPK];
__device__ float g_WdecT[(size_t)DLATENT * DMODEL];  // 37.7 MB

// ============================================================
// Kernel 0: transpose W_dec [768,12288] -> W_decT [12288,768]
// ============================================================
__global__ void transpose_wdec(const float* __restrict__ Wdec) {
    __shared__ float tile[32][33];
    int l0 = blockIdx.x * 32;
    int d0 = blockIdx.y * 32;
    int tx = threadIdx.x, ty = threadIdx.y;   // (32,8)
    #pragma unroll
    for (int r = 0; r < 32; r += 8)
        tile[ty + r][tx] = Wdec[(size_t)(d0 + ty + r) * DLATENT + l0 + tx];
    __syncthreads();
    #pragma unroll
    for (int r = 0; r < 32; r += 8)
        g_WdecT[(size_t)(l0 + ty + r) * DMODEL + d0 + tx] = tile[tx][ty + r];
}

// ============================================================
// Kernel 1: encode GEMM  latents = X * W_enc^T + b_enc (tf32)
//   CTA 128x128x32, 3-stage cp.async pipeline, ldmatrix fragments.
// ============================================================
#define BM 128
#define BN 128
#define BK 32
#define BKP 36                      // padded row stride (floats)
#define STAGE_FLOATS (2 * BM * BKP) // A + B per stage = 9216 floats
#define STAGE_BYTES  (STAGE_FLOATS * 4)
#define NSTAGE 3
#define GEMM_SMEM (NSTAGE * STAGE_BYTES)   // 110592 bytes

__device__ __forceinline__ void cp16(uint32_t dst, const float* src) {
    asm volatile("cp.async.cg.shared.global [%0], [%1], 16;" :: "r"(dst), "l"(src));
}
__device__ __forceinline__ void ldsm4(uint32_t& r0, uint32_t& r1,
                                      uint32_t& r2, uint32_t& r3, uint32_t addr) {
    asm volatile("ldmatrix.sync.aligned.m8n8.x4.shared.b16 {%0,%1,%2,%3}, [%4];"
                 : "=r"(r0), "=r"(r1), "=r"(r2), "=r"(r3) : "r"(addr));
}

extern __shared__ float dynsmem[];

__global__ __launch_bounds__(256)
void encode_gemm(const float* __restrict__ X,
                 const float* __restrict__ W,
                 const float* __restrict__ benc) {
    const int t    = threadIdx.x;
    const int bm   = blockIdx.y;
    const int bn   = blockIdx.x;
    const int w    = t >> 5;
    const int lane = t & 31;
    const int wm   = (w >> 2) * 64;
    const int wn   = (w & 3) * 32;
    const int grp  = lane >> 2;
    const int qid  = lane & 3;

    const uint32_t smem_base = (uint32_t)__cvta_generic_to_shared(dynsmem);

    const int lrow = t >> 3;          // 0..31
    const int lk   = (t & 7) * 4;     // 0,4,...,28
    const float* Ag = X + (size_t)(bm * BM + lrow) * DMODEL + lk;
    const float* Bg = W + (size_t)(bn * BN + lrow) * DMODEL + lk;
    const uint32_t sA = smem_base + (lrow * BKP + lk) * 4;
    const uint32_t sB = sA + BM * BKP * 4;

    const int arow = lane & 15;
    const int acol = (lane & 16) ? 4 : 0;
    const int brow = (lane & 7) + ((lane & 16) >> 1);
    const int bcol = (lane & 8) ? 4 : 0;
    const uint32_t aBase = smem_base + ((wm + arow) * BKP + acol) * 4;
    const uint32_t bBase = smem_base + BM * BKP * 4 + ((wn + brow) * BKP + bcol) * 4;

    float c[4][4][4];
    #pragma unroll
    for (int i = 0; i < 4; ++i)
        #pragma unroll
        for (int j = 0; j < 4; ++j)
            #pragma unroll
            for (int q = 0; q < 4; ++q) c[i][j][q] = 0.f;

    const int KT = DMODEL / BK;       // 24

    #pragma unroll
    for (int s = 0; s < NSTAGE - 1; ++s) {
        #pragma unroll
        for (int r = 0; r < 4; ++r) {
            cp16(sA + s * STAGE_BYTES + r * 32 * BKP * 4, Ag + s * BK + (size_t)r * 32 * DMODEL);
            cp16(sB + s * STAGE_BYTES + r * 32 * BKP * 4, Bg + s * BK + (size_t)r * 32 * DMODEL);
        }
        asm volatile("cp.async.commit_group;");
    }

    for (int kt = 0; kt < KT; ++kt) {
        asm volatile("cp.async.wait_group %0;" :: "n"(NSTAGE - 2));
        __syncthreads();

        {
            int nxt = kt + NSTAGE - 1;
            if (nxt < KT) {
                int s = nxt % NSTAGE;
                #pragma unroll
                for (int r = 0; r < 4; ++r) {
                    cp16(sA + s * STAGE_BYTES + r * 32 * BKP * 4, Ag + nxt * BK + (size_t)r * 32 * DMODEL);
                    cp16(sB + s * STAGE_BYTES + r * 32 * BKP * 4, Bg + nxt * BK + (size_t)r * 32 * DMODEL);
                }
            }
            asm volatile("cp.async.commit_group;");
        }

        const uint32_t stoff = (uint32_t)(kt % NSTAGE) * STAGE_BYTES;

        #pragma unroll
        for (int ks = 0; ks < 4; ++ks) {
            const int k8 = ks * 8;
            uint32_t a[4][4], bf[4][2];
            #pragma unroll
            for (int i = 0; i < 4; ++i)
                ldsm4(a[i][0], a[i][1], a[i][2], a[i][3],
                      aBase + stoff + (i * 16 * BKP + k8) * 4);
            #pragma unroll
            for (int jp = 0; jp < 2; ++jp)
                ldsm4(bf[2 * jp][0], bf[2 * jp][1], bf[2 * jp + 1][0], bf[2 * jp + 1][1],
                      bBase + stoff + (jp * 16 * BKP + k8) * 4);
            #pragma unroll
            for (int i = 0; i < 4; ++i)
                #pragma unroll
                for (int j = 0; j < 4; ++j) {
                    asm volatile(
                        "mma.sync.aligned.m16n8k8.row.col.f32.tf32.tf32.f32 "
                        "{%0,%1,%2,%3}, {%4,%5,%6,%7}, {%8,%9}, {%0,%1,%2,%3};"
                        : "+f"(c[i][j][0]), "+f"(c[i][j][1]),
                          "+f"(c[i][j][2]), "+f"(c[i][j][3])
                        : "r"(a[i][0]), "r"(a[i][1]), "r"(a[i][2]), "r"(a[i][3]),
                          "r"(bf[j][0]), "r"(bf[j][1]));
                }
        }
    }

    #pragma unroll
    for (int j = 0; j < 4; ++j) {
        int cg = bn * BN + wn + j * 8 + 2 * qid;
        float b0 = benc[cg], b1 = benc[cg + 1];
        #pragma unroll
        for (int i = 0; i < 4; ++i) {
            int rg = bm * BM + wm + i * 16 + grp;
            float2 v0 = make_float2(c[i][j][0] + b0, c[i][j][1] + b1);
            float2 v1 = make_float2(c[i][j][2] + b0, c[i][j][3] + b1);
            *(float2*)&g_lat[(size_t)rg * DLATENT + cg]       = v0;
            *(float2*)&g_lat[(size_t)(rg + 8) * DLATENT + cg] = v1;
        }
    }
}

// ============================================================
// Kernel 2: per-row top-32 CANDIDATE indices from tf32 latents.
// Per-thread sorted top-32 (registers) -> transposed smem lists
// (conflict-free) -> 32-round k-way merge over the 128 list heads.
// ============================================================
__global__ __launch_bounds__(128)
void topk_cand_kernel() {
    const int row  = blockIdx.x;
    const int t    = threadIdx.x;   // 128
    const int w    = t >> 5;
    const int lane = t & 31;
    const float* lat = g_lat + (size_t)row * DLATENT;

    // ---- phase 1: per-thread sorted (descending) top-32 in registers
    float lv[KCAND];
    int   li[KCAND];
    #pragma unroll
    for (int k = 0; k < KCAND; ++k) { lv[k] = -3.4e38f; li[k] = 0; }

    #pragma unroll 4
    for (int col = t; col < DLATENT; col += 128) {
        float v = lat[col];
        if (v > lv[KCAND - 1]) {
            int p = KCAND - 1;
            while (p > 0 && lv[p - 1] < v) {
                lv[p] = lv[p - 1]; li[p] = li[p - 1]; --p;
            }
            lv[p] = v; li[p] = col;
        }
    }

    // ---- phase 2: write lists TRANSPOSED: sv[k*128 + t] (stride-1 across lanes)
    __shared__ float sv[KCAND * 128];
    __shared__ int   si[KCAND * 128];
    #pragma unroll
    for (int k = 0; k < KCAND; ++k) { sv[k * 128 + t] = lv[k]; si[k * 128 + t] = li[k]; }

    __shared__ float wv[4];
    __shared__ int   wt[4];
    __shared__ int   winner_s;
    __syncthreads();

    // ---- phase 3: 32-round merge of 128 sorted lists.
    // Global max of all remaining candidates is always among the 128 heads.
    int p = 0;   // this thread's head pointer
    for (int kk = 0; kk < KCAND; ++kk) {
        float h = (p < KCAND) ? sv[p * 128 + t] : -3.4e38f;
        // warp argmax (value, owning thread)
        float v = h; int vt = t;
        #pragma unroll
        for (int off = 16; off > 0; off >>= 1) {
            float ov = __shfl_down_sync(0xffffffffu, v, off);
            int   ot = __shfl_down_sync(0xffffffffu, vt, off);
            if (ov > v) { v = ov; vt = ot; }
        }
        if (lane == 0) { wv[w] = v; wt[w] = vt; }
        __syncthreads();
        if (t == 0) {
            float m = wv[0]; int mt = wt[0];
            #pragma unroll
            for (int q = 1; q < 4; ++q)
                if (wv[q] > m) { m = wv[q]; mt = wt[q]; }
            winner_s = mt;
        }
        __syncthreads();
        if (t == winner_s) {
            g_cidx[row * KCAND + kk] = si[p * 128 + t];
            ++p;
        }
    }
}

// ============================================================
// Kernel 3: fp64 refinement — recompute the 32 candidate latents
// exactly, select the true top-20.
// ============================================================
__global__ __launch_bounds__(256)
void refine_kernel(const float* __restrict__ X,
                   const float* __restrict__ W,
                   const float* __restrict__ benc) {
    const int row  = blockIdx.x;
    const int t    = threadIdx.x;    // 256 = 8 warps
    const int w    = t >> 5;
    const int lane = t & 31;

    __shared__ float  xs[DMODEL];
    __shared__ double cv[KCAND];
    __shared__ int    ci[KCAND];

    for (int j = t; j < DMODEL; j += 256)
        xs[j] = X[(size_t)row * DMODEL + j];
    __syncthreads();

    #pragma unroll
    for (int cb = 0; cb < KCAND; cb += 8) {
        int c   = cb + w;
        int idx = g_cidx[row * KCAND + c];
        const float* wr = W + (size_t)idx * DMODEL;
        double acc = 0.0;
        #pragma unroll
        for (int j = 0; j < DMODEL / 32; ++j)
            acc += (double)xs[lane + j * 32] * (double)wr[lane + j * 32];
        #pragma unroll
        for (int off = 16; off > 0; off >>= 1)
            acc += __shfl_down_sync(0xffffffffu, acc, off);
        if (lane == 0) { cv[c] = acc + (double)benc[idx]; ci[c] = idx; }
    }
    __syncthreads();

    if (t == 0) {
        #pragma unroll
        for (int kk = 0; kk < TOPK; ++kk) {
            double m = -1e300; int ms = 0;
            #pragma unroll
            for (int k = 0; k < KCAND; ++k)
                if (cv[k] > m) { m = cv[k]; ms = k; }
            g_vals[row * TOPK + kk] = (float)m;
            g_idx [row * TOPK + kk] = ci[ms];
            cv[ms] = -1e300;
        }
    }
}

// ============================================================
// Kernel 4: decode  out[n,d] = b_dec[d] + sum_k vals[n,k]*W_decT[idx[n,k], d]
// ============================================================
__global__ __launch_bounds__(256)
void decode_kernel(const float* __restrict__ bdec,
                   float* __restrict__ out) {
    const int row = blockIdx.x;
    const int t   = threadIdx.x;   // 256
    __shared__ float v[TOPK];
    __shared__ int   id[TOPK];
    if (t < TOPK) { v[t] = g_vals[row * TOPK + t]; id[t] = g_idx[row * TOPK + t]; }
    __syncthreads();

    #pragma unroll
    for (int r = 0; r < 3; ++r) {
        int d = t + r * 256;
        float acc = bdec[d];
        #pragma unroll
        for (int k = 0; k < TOPK; ++k)
            acc += v[k] * g_WdecT[(size_t)id[k] * DMODEL + d];
        out[(size_t)row * DMODEL + d] = acc;
    }
}

// ============================================================
extern "C" void kernel_launch(void* const* d_in, const int* in_sizes, int n_in,
                              void* d_out, int out_size) {
    const float* x     = (const float*)d_in[0];
    const float* W_enc = (const float*)d_in[1];
    const float* b_enc = (const float*)d_in[2];
    const float* W_dec = (const float*)d_in[3];
    const float* b_dec = (const float*)d_in[4];
    float* out = (float*)d_out;

    cudaFuncSetAttribute(encode_gemm, cudaFuncAttributeMaxDynamicSharedMemorySize, GEMM_SMEM);

    transpose_wdec<<<dim3(DLATENT / 32, DMODEL / 32), dim3(32, 8)>>>(W_dec);
    encode_gemm<<<dim3(DLATENT / BN, N_ROWS / BM), 256, GEMM_SMEM>>>(x, W_enc, b_enc);
    topk_cand_kernel<<<N_ROWS, 128>>>();
    refine_kernel<<<N_ROWS, 256>>>(x, W_enc, b_enc);
    decode_kernel<<<N_ROWS, 256>>>(b_dec, out);
}